// round 3
// baseline (speedup 1.0000x reference)
#include <cuda_runtime.h>

// x (B,L,C,H,W) = (2,24,32,128,256) fp32, params (2,C,R) = (2,32,32) fp32.
// Exact causal FIR conv along L (reference rfft(48) path has no circular
// aliasing since 2L-1 = 47 <= 48).
//
// Persistent single-wave kernel: 296 blocks (148 SMs x 2 CTAs), grid-stride
// over 2048 tiles of 256 float4-pixels. Eliminates the 7-wave launch/transition
// bubbles that left ~29% of DRAM cycles idle in the plain-grid version.

#define B_ 2
#define L_ 24
#define C_ 32
#define H_ 128
#define W_ 256
#define R_ 32

#define NBLOCKS 296                      // 148 SMs * 2 resident CTAs
#define NTILES  (B_ * C_ * H_ * (W_/4) / 256)   // 2048

__global__ __launch_bounds__(256, 2)
void ConvLRU_persist_kernel(const float4* __restrict__ x,
                            const float*  __restrict__ p,
                            float4* __restrict__ y) {
    constexpr int W4      = W_ / 4;       // 64
    constexpr int HW4     = H_ * W4;      // 8192 (divisible by 256 -> c uniform per tile)
    constexpr int strideL = C_ * HW4;     // float4 stride between consecutive l

    const int lane = threadIdx.x & 31;    // = rank r for k-compute
    const int wrp  = threadIdx.x >> 5;    // warp id 0..7

    __shared__ float sk[L_];

    for (int tile = blockIdx.x; tile < NTILES; tile += NBLOCKS) {
        int gid = tile * 256 + threadIdx.x;     // over B*C*HW4 = 524288
        int hw  = gid % HW4;
        int bc  = gid / HW4;
        int c   = bc % C_;
        int b   = bc / C_;

        __syncthreads();   // WAR: previous tile's sk reads done before rewrite

        // ---- k[c][t] = sum_r gamma * exp(-t*nu) * cos(t*theta) ----
        {
            float nu_log    = p[c * R_ + lane];
            float theta_log = p[C_ * R_ + c * R_ + lane];
            float nu    = __expf(nu_log);
            float theta = __expf(theta_log);
            float lam2  = __expf(-2.0f * nu);
            float gamma = sqrtf(fmaxf(1.0f - lam2, 1e-12f));
#pragma unroll
            for (int j = 0; j < 3; j++) {
                int   t  = 8 * j + wrp;        // each warp covers t = w, w+8, w+16
                float tf = (float)t;
                float term = gamma * __expf(-tf * nu) * __cosf(tf * theta);
#pragma unroll
                for (int off = 16; off > 0; off >>= 1)
                    term += __shfl_xor_sync(0xFFFFFFFFu, term, off);
                if (lane == 0) sk[t] = term;
            }
        }

        // ---- issue all 24 sequence loads (independent; deep MLP) ----
        int base = (b * (L_ * C_) + c) * HW4 + hw;   // float4 index of l=0

        float4 xv[L_];
#pragma unroll
        for (int l = 0; l < L_; l++) {
            xv[l] = __ldcs(&x[base + l * strideL]);
        }

        __syncthreads();   // sk visible; xv loads still in flight

        // ---- triangular causal MAC + streaming stores ----
#pragma unroll
        for (int l = 0; l < L_; l++) {
            float4 acc = make_float4(0.f, 0.f, 0.f, 0.f);
#pragma unroll
            for (int t = 0; t <= l; t++) {
                float  kv = sk[t];
                float4 xs = xv[l - t];
                acc.x = fmaf(kv, xs.x, acc.x);
                acc.y = fmaf(kv, xs.y, acc.y);
                acc.z = fmaf(kv, xs.z, acc.z);
                acc.w = fmaf(kv, xs.w, acc.w);
            }
            __stcs(&y[base + l * strideL], acc);
        }
    }
}

extern "C" void kernel_launch(void* const* d_in, const int* in_sizes, int n_in,
                              void* d_out, int out_size) {
    const float* x = (const float*)d_in[0];        // (B,L,C,H,W)
    const float* p = (const float*)d_in[1];        // (2,C,R)
    float* y = (float*)d_out;

    ConvLRU_persist_kernel<<<NBLOCKS, 256>>>((const float4*)x, p, (float4*)y);
}

// round 4
// speedup vs baseline: 1.1275x; 1.1275x over previous
#include <cuda_runtime.h>

// x (B,L,C,H,W) = (2,24,32,128,256) fp32, params (2,C,R) = (2,32,32) fp32.
// Exact causal FIR conv along L (reference rfft(48) path has no circular
// aliasing since 2L-1 = 47 <= 48).
//
// Plain grid (persistent variant regressed: per-tile barriers bubble DRAM).
// Loads issued FIRST (MUFU k-compute hides under DRAM latency), MAC uses
// packed fma.rn.f32x2 to halve FFMA issue count.

#define B_ 2
#define L_ 24
#define C_ 32
#define H_ 128
#define W_ 256
#define R_ 32

__global__ __launch_bounds__(256, 2)
void ConvLRU_fused_kernel(const ulonglong2* __restrict__ x,
                          const float*      __restrict__ p,
                          ulonglong2*       __restrict__ y) {
    constexpr int W4      = W_ / 4;       // 64
    constexpr int HW4     = H_ * W4;      // 8192 (divisible by 256 -> c uniform per block)
    constexpr int strideL = C_ * HW4;     // 128-bit stride between consecutive l

    int gid = blockIdx.x * 256 + threadIdx.x;   // over B*C*HW4 = 524288
    int hw  = gid % HW4;
    int bc  = gid / HW4;
    int c   = bc % C_;
    int b   = bc / C_;

    __shared__ float sk[L_];

    // ---- issue all 24 sequence loads first (deep MLP, evict-first) ----
    int base = (b * (L_ * C_) + c) * HW4 + hw;  // 128-bit index of l=0 sample

    ulonglong2 xv[L_];
#pragma unroll
    for (int l = 0; l < L_; l++) {
        xv[l] = __ldcs(&x[base + l * strideL]);
    }

    // ---- k[c][t] = sum_r gamma*exp(-t*nu)*cos(t*theta); hides under loads ----
    {
        int lane = threadIdx.x & 31;       // = rank r
        int wrp  = threadIdx.x >> 5;       // warp id 0..7
        float nu_log    = p[c * R_ + lane];
        float theta_log = p[C_ * R_ + c * R_ + lane];
        float nu    = __expf(nu_log);
        float theta = __expf(theta_log);
        float lam2  = __expf(-2.0f * nu);
        float gamma = sqrtf(fmaxf(1.0f - lam2, 1e-12f));
#pragma unroll
        for (int j = 0; j < 3; j++) {
            int   t  = 8 * j + wrp;        // each warp covers t = w, w+8, w+16
            float tf = (float)t;
            float term = gamma * __expf(-tf * nu) * __cosf(tf * theta);
#pragma unroll
            for (int off = 16; off > 0; off >>= 1)
                term += __shfl_xor_sync(0xFFFFFFFFu, term, off);
            if (lane == 0) sk[t] = term;
        }
    }

    __syncthreads();   // sk visible; xv loads still in flight

    // ---- triangular causal MAC with packed f32x2 FMAs + streaming stores ----
#pragma unroll
    for (int l = 0; l < L_; l++) {
        unsigned long long a0 = 0ull;      // {0.f, 0.f}
        unsigned long long a1 = 0ull;
#pragma unroll
        for (int t = 0; t <= l; t++) {
            float kv = sk[t];
            unsigned long long kk;
            // duplicate k into both halves (non-volatile -> CSE across l)
            asm("mov.b64 %0, {%1, %1};" : "=l"(kk) : "r"(__float_as_uint(kv)));
            asm("fma.rn.f32x2 %0, %1, %2, %0;" : "+l"(a0) : "l"(xv[l - t].x), "l"(kk));
            asm("fma.rn.f32x2 %0, %1, %2, %0;" : "+l"(a1) : "l"(xv[l - t].y), "l"(kk));
        }
        __stcs(&y[base + l * strideL], make_ulonglong2(a0, a1));
    }
}

extern "C" void kernel_launch(void* const* d_in, const int* in_sizes, int n_in,
                              void* d_out, int out_size) {
    const float* x = (const float*)d_in[0];        // (B,L,C,H,W)
    const float* p = (const float*)d_in[1];        // (2,C,R)
    float* y = (float*)d_out;

    constexpr int total4 = B_ * C_ * H_ * (W_ / 4);  // 524288
    ConvLRU_fused_kernel<<<total4 / 256, 256>>>(
        (const ulonglong2*)x, p, (ulonglong2*)y);
}

// round 5
// speedup vs baseline: 1.1394x; 1.0106x over previous
#include <cuda_runtime.h>

// x (B,L,C,H,W) = (2,24,32,128,256) fp32, params (2,C,R) = (2,32,32) fp32.
// Exact causal FIR conv along L (reference rfft(48) path has no circular
// aliasing since 2L-1 = 47 <= 48).
//
// R5: float2 per thread (48-reg x-window instead of 96) to fit 3 CTAs/SM and
// lift occupancy 21.9% -> ~33%, feeding DRAM more overlapping load batches.
// Keeps R4's wins: loads issued first, MUFU k-compute hidden under them,
// packed fma.rn.f32x2 MAC, streaming ld/st.

#define B_ 2
#define L_ 24
#define C_ 32
#define H_ 128
#define W_ 256
#define R_ 32

__global__ __launch_bounds__(256, 3)
void ConvLRU_fused_kernel(const unsigned long long* __restrict__ x,
                          const float*              __restrict__ p,
                          unsigned long long*       __restrict__ y) {
    constexpr int W2      = W_ / 2;       // 128
    constexpr int HW2     = H_ * W2;      // 16384 (divisible by 256 -> c uniform/block)
    constexpr int strideL = C_ * HW2;     // 64-bit stride between consecutive l

    int gid = blockIdx.x * 256 + threadIdx.x;   // over B*C*HW2 = 1048576
    int hw  = gid % HW2;
    int bc  = gid / HW2;
    int c   = bc % C_;
    int b   = bc / C_;

    __shared__ float sk[L_];

    // ---- issue all 24 sequence loads first (deep MLP, evict-first) ----
    int base = (b * (L_ * C_) + c) * HW2 + hw;  // 64-bit-elem index of l=0

    unsigned long long xv[L_];
#pragma unroll
    for (int l = 0; l < L_; l++) {
        xv[l] = __ldcs(&x[base + l * strideL]);
    }

    // ---- k[c][t] = sum_r gamma*exp(-t*nu)*cos(t*theta); hides under loads ----
    {
        int lane = threadIdx.x & 31;       // = rank r
        int wrp  = threadIdx.x >> 5;       // warp id 0..7
        float nu_log    = p[c * R_ + lane];
        float theta_log = p[C_ * R_ + c * R_ + lane];
        float nu    = __expf(nu_log);
        float theta = __expf(theta_log);
        float lam2  = __expf(-2.0f * nu);
        float gamma = sqrtf(fmaxf(1.0f - lam2, 1e-12f));
#pragma unroll
        for (int j = 0; j < 3; j++) {
            int   t  = 8 * j + wrp;        // each warp covers t = w, w+8, w+16
            float tf = (float)t;
            float term = gamma * __expf(-tf * nu) * __cosf(tf * theta);
#pragma unroll
            for (int off = 16; off > 0; off >>= 1)
                term += __shfl_xor_sync(0xFFFFFFFFu, term, off);
            if (lane == 0) sk[t] = term;
        }
    }

    __syncthreads();   // sk visible; xv loads still in flight

    // ---- triangular causal MAC with packed f32x2 FMAs + streaming stores ----
#pragma unroll
    for (int l = 0; l < L_; l++) {
        unsigned long long acc = 0ull;     // {0.f, 0.f}
#pragma unroll
        for (int t = 0; t <= l; t++) {
            float kv = sk[t];
            unsigned long long kk;
            asm("mov.b64 %0, {%1, %1};" : "=l"(kk) : "r"(__float_as_uint(kv)));
            asm("fma.rn.f32x2 %0, %1, %2, %0;" : "+l"(acc) : "l"(xv[l - t]), "l"(kk));
        }
        __stcs(&y[base + l * strideL], acc);
    }
}

extern "C" void kernel_launch(void* const* d_in, const int* in_sizes, int n_in,
                              void* d_out, int out_size) {
    const float* x = (const float*)d_in[0];        // (B,L,C,H,W)
    const float* p = (const float*)d_in[1];        // (2,C,R)
    float* y = (float*)d_out;

    constexpr int total2 = B_ * C_ * H_ * (W_ / 2);  // 1048576
    ConvLRU_fused_kernel<<<total2 / 256, 256>>>(
        (const unsigned long long*)x, p, (unsigned long long*)y);
}